// round 1
// baseline (speedup 1.0000x reference)
#include <cuda_runtime.h>

// Problem constants (fixed shapes: x (2,21,256,256), image (2,3,256,256))
#define NPT    131072          // 2*256*256 points
#define NC     21              // channels
#define HW     65536           // 256*256
#define DP1    6               // d+1
#define MAXLAT (NPT*DP1)       // 786432 max lattice points
#define CPAD   32              // padded channels per lattice row (128B rows)
#define HBITS  22
#define HSIZE  (1u<<HBITS)     // 4M slots
#define HMASK  (HSIZE-1u)
#define KEMPTY 0xFFFFFFFFFFFFFFFFull

// ---- static device scratch (no runtime allocation allowed) ----
__device__ unsigned long long g_hkeys[HSIZE];
__device__ int                g_hvals[HSIZE];
__device__ unsigned long long g_rowkey[MAXLAT];
__device__ int                g_slot[NPT*DP1];
__device__ int                g_idx[NPT*DP1];
__device__ float              g_bary[NPT*DP1];
__device__ __align__(256) float g_lat0[MAXLAT*CPAD];
__device__ __align__(256) float g_lat1[MAXLAT*CPAD];
__device__ int                g_count;

__device__ __forceinline__ unsigned hhash(unsigned long long k){
    return (unsigned)((k * 0x9E3779B97F4A7C15ull) >> (64 - HBITS));
}

// Insert key; return the slot that ends up holding it.
__device__ __forceinline__ int ht_insert(unsigned long long key){
    unsigned s = hhash(key);
    while (true){
        unsigned long long cur = g_hkeys[s];
        if (cur == key) return (int)s;
        if (cur == KEMPTY){
            unsigned long long old = atomicCAS(&g_hkeys[s], KEMPTY, key);
            if (old == KEMPTY || old == key) return (int)s;
        }
        s = (s + 1) & HMASK;
    }
}

// Lookup (table immutable at this point). Returns lattice index or -1.
__device__ __forceinline__ int ht_lookup(unsigned long long key){
    unsigned s = hhash(key);
    while (true){
        unsigned long long cur = g_hkeys[s];
        if (cur == key) return g_hvals[s];
        if (cur == KEMPTY) return -1;
        s = (s + 1) & HMASK;
    }
}

// ---- K0: reset hash table, lattice buffer, counter ----
__global__ void k_init(){
    unsigned t = blockIdx.x * blockDim.x + threadIdx.x;
    unsigned stride = gridDim.x * blockDim.x;
    for (unsigned i = t; i < HSIZE; i += stride) g_hkeys[i] = KEMPTY;
    float4 z = make_float4(0.f, 0.f, 0.f, 0.f);
    float4* p = (float4*)g_lat0;
    const unsigned n4 = (unsigned)(MAXLAT * CPAD / 4);
    for (unsigned i = t; i < n4; i += stride) p[i] = z;
    if (t == 0) g_count = 0;
}

// ---- K1: per point: elevate, simplex, barycentric, key insert ----
__global__ void k_point(const float* __restrict__ img){
    int n = blockIdx.x * blockDim.x + threadIdx.x;
    if (n >= NPT) return;
    int b  = n >> 16;
    int hw = n & 65535;
    int h  = hw >> 8;
    int w  = hw & 255;

    const float* ip = img + b * 3 * HW + hw;
    // feats * scale (scale from DenseCRF elevation, fp64 constants -> fp32)
    float cf[5];
    cf[0] = ((float)w / 80.0f) * (float)3.4641016151377544;
    cf[1] = ((float)h / 80.0f) * (float)2.0;
    cf[2] = (ip[0]      / 13.0f) * (float)1.4142135623730951;
    cf[3] = (ip[HW]     / 13.0f) * (float)1.0954451150103321;
    cf[4] = (ip[2*HW]   / 13.0f) * (float)0.8944271909999159;

    float el[6];
    el[0] =  cf[0] + cf[1] + cf[2] + cf[3] + cf[4];
    el[1] = -1.f*cf[0] + cf[1] + cf[2] + cf[3] + cf[4];
    el[2] = -2.f*cf[1] + cf[2] + cf[3] + cf[4];
    el[3] = -3.f*cf[2] + cf[3] + cf[4];
    el[4] = -4.f*cf[3] + cf[4];
    el[5] = -5.f*cf[4];

    // closest zero-colored lattice point
    float rem0[6]; float s = 0.f;
#pragma unroll
    for (int j = 0; j < 6; j++){
        float v    = el[j] / 6.0f;
        float up   = ceilf(v)  * 6.0f;
        float down = floorf(v) * 6.0f;
        rem0[j] = ((up - el[j]) < (el[j] - down)) ? up : down;
        s += rem0[j];
    }
    int ssum = (int)rintf(s / 6.0f);

    float di[6];
#pragma unroll
    for (int j = 0; j < 6; j++) di[j] = el[j] - rem0[j];

    int rank[6];
#pragma unroll
    for (int i = 0; i < 6; i++){
        int r = 0;
#pragma unroll
        for (int j = 0; j < 6; j++){
            if (j == i) continue;
            if (j > i) r += (di[i] <  di[j]);
            else       r += (di[i] <= di[j]);
        }
        rank[i] = r + ssum;
    }
#pragma unroll
    for (int j = 0; j < 6; j++){
        if (rank[j] < 0)      { rank[j] += 6; rem0[j] += 6.f; }
        else if (rank[j] > 5) { rank[j] -= 6; rem0[j] -= 6.f; }
    }

    // barycentric weights
    float bary[7] = {0.f,0.f,0.f,0.f,0.f,0.f,0.f};
#pragma unroll
    for (int i = 0; i < 6; i++){
        float t = (el[i] - rem0[i]) / 6.0f;
        bary[5 - rank[i]] += t;
        bary[6 - rank[i]] -= t;
    }
    bary[0] = (bary[0] + 1.0f) + bary[6];

    long long ri[5];
#pragma unroll
    for (int i = 0; i < 5; i++) ri[i] = (long long)llrintf(rem0[i]);

    // simplex vertex keys -> hash insert
#pragma unroll
    for (int r = 0; r < 6; r++){
        g_bary[n*DP1 + r] = bary[r];
        long long pk = ((long long)b) << 60;
#pragma unroll
        for (int i = 0; i < 5; i++){
            long long ki = ri[i] + r - ((rank[i] > 5 - r) ? 6 : 0);
            pk += (ki + 2048) << (12 * i);
        }
        g_slot[n*DP1 + r] = ht_insert((unsigned long long)pk);
    }
}

// ---- K2: assign dense lattice indices (block-aggregated; ~1024 atomics) ----
__global__ void k_assign(){
    const int SPT = 16;  // slots per thread; block covers 4096 slots
    __shared__ int wsum[8];
    __shared__ int blockBase;
    int t    = threadIdx.x;
    int base = blockIdx.x * (256 * SPT);

    int cnt = 0;
#pragma unroll
    for (int k = 0; k < SPT; k++)
        cnt += (g_hkeys[base + k*256 + t] != KEMPTY) ? 1 : 0;

    int lane = t & 31, wid = t >> 5;
    int pref = cnt;
#pragma unroll
    for (int off = 1; off < 32; off <<= 1){
        int y = __shfl_up_sync(0xffffffffu, pref, off);
        if (lane >= off) pref += y;
    }
    if (lane == 31) wsum[wid] = pref;
    __syncthreads();
    if (t < 8){
        int v = wsum[t];
#pragma unroll
        for (int off = 1; off < 8; off <<= 1){
            int y = __shfl_up_sync(0xffu, v, off);
            if (t >= off) v += y;
        }
        wsum[t] = v;
    }
    __syncthreads();
    if (t == 0) blockBase = atomicAdd(&g_count, wsum[7]);
    __syncthreads();

    int idx = blockBase + (wid ? wsum[wid-1] : 0) + (pref - cnt);
    for (int k = 0; k < SPT; k++){
        int sIdx = base + k*256 + t;
        unsigned long long key = g_hkeys[sIdx];
        if (key != KEMPTY){
            g_hvals[sIdx]  = idx;
            g_rowkey[idx]  = key;
            idx++;
        }
    }
}

// ---- K3: splat (warp per point; lanes = channels; coalesced atomics) ----
__global__ void k_splat(const float* __restrict__ x){
    int gw   = (blockIdx.x * blockDim.x + threadIdx.x) >> 5;
    int lane = threadIdx.x & 31;
    if (gw >= NPT) return;
    int n  = gw;
    int b  = n >> 16;
    int hw = n & 65535;

    float val = 0.f;
    if (lane < NC) val = x[(b*NC + lane) * HW + hw];

    int   myidx = 0;
    float myb   = 0.f;
    if (lane < DP1){
        int slot = g_slot[n*DP1 + lane];
        myidx = g_hvals[slot];
        g_idx[n*DP1 + lane] = myidx;
        myb   = g_bary[n*DP1 + lane];
    }
#pragma unroll
    for (int r = 0; r < DP1; r++){
        int   idx = __shfl_sync(0xffffffffu, myidx, r);
        float wgt = __shfl_sync(0xffffffffu, myb,   r);
        if (lane < NC) atomicAdd(&g_lat0[idx * CPAD + lane], wgt * val);
    }
}

// ---- K4: one blur pass along lattice direction j ----
__global__ void k_blur(int j){
    const float* __restrict__ in  = (j & 1) ? g_lat1 : g_lat0;
    float* __restrict__       out = (j & 1) ? g_lat0 : g_lat1;
    int lane   = threadIdx.x & 31;
    int warp   = (blockIdx.x * blockDim.x + threadIdx.x) >> 5;
    int nwarps = (gridDim.x * blockDim.x) >> 5;
    int U = g_count;

    const long long ONES = 0x0001001001001001LL;  // +1 in each of 5 coord fields
    long long delta = (j < 5) ? (6LL << (12 * j)) : 0LL;
    unsigned long long d1 = (unsigned long long)(ONES - delta);

    for (int i = warp; i < U; i += nwarps){
        unsigned long long key = g_rowkey[i];
        int n1 = -1, n2 = -1;
        if (lane == 0)      n1 = ht_lookup(key + d1);
        else if (lane == 1) n2 = ht_lookup(key - d1);
        n1 = __shfl_sync(0xffffffffu, n1, 0);
        n2 = __shfl_sync(0xffffffffu, n2, 1);
        if (lane < NC){
            float a  = in[i * CPAD + lane];
            float v1 = (n1 >= 0) ? in[n1 * CPAD + lane] : 0.f;
            float v2 = (n2 >= 0) ? in[n2 * CPAD + lane] : 0.f;
            out[i * CPAD + lane] = a + 0.5f * (v1 + v2);
        }
    }
}

// ---- K5: slice + transpose to NCHW output ----
__global__ void k_slice(float* __restrict__ out){
    __shared__ float sm[32][23];  // stride 23: conflict-free column reads
    int warp = threadIdx.x >> 5, lane = threadIdx.x & 31;
    int n0 = blockIdx.x * 32;
    const float ALPHA = (float)(32.0 / 33.0);  // 1/(1+2^-5)

#pragma unroll
    for (int p = 0; p < 4; p++){
        int il = warp * 4 + p;
        int n  = n0 + il;
        int   myidx = 0;
        float myb   = 0.f;
        if (lane < DP1){
            myidx = g_idx[n*DP1 + lane];
            myb   = g_bary[n*DP1 + lane];
        }
        float acc = 0.f;
#pragma unroll
        for (int r = 0; r < DP1; r++){
            int   idx = __shfl_sync(0xffffffffu, myidx, r);
            float bw  = __shfl_sync(0xffffffffu, myb,   r);
            if (lane < NC) acc += bw * g_lat0[idx * CPAD + lane];
        }
        if (lane < NC) sm[il][lane] = ALPHA * acc;
    }
    __syncthreads();

    for (int t = threadIdx.x; t < NC * 32; t += 256){
        int c = t >> 5, i = t & 31;
        int n  = n0 + i;
        int b  = n >> 16;
        int hw = n & 65535;
        out[(b*NC + c) * HW + hw] = sm[i][c];
    }
}

extern "C" void kernel_launch(void* const* d_in, const int* in_sizes, int n_in,
                              void* d_out, int out_size){
    const float* x   = (const float*)d_in[0];   // (2,21,256,256)
    const float* img = (const float*)d_in[1];   // (2,3,256,256)
    float* out = (float*)d_out;

    k_init  <<<4096, 256>>>();
    k_point <<<NPT/256, 256>>>(img);
    k_assign<<<HSIZE/(256*16), 256>>>();
    k_splat <<<NPT/8, 256>>>(x);
    for (int j = 0; j < 6; j++)
        k_blur<<<4736, 256>>>(j);
    k_slice <<<NPT/32, 256>>>(out);
}

// round 2
// speedup vs baseline: 1.6671x; 1.6671x over previous
#include <cuda_runtime.h>

// Problem constants (fixed shapes: x (2,21,256,256), image (2,3,256,256))
#define NPT    131072          // 2*256*256 points
#define NC     21              // channels
#define HW     65536           // 256*256
#define DP1    6               // d+1
#define MAXLAT (NPT*DP1)       // 786432 max lattice points
#define CPAD   24              // padded channels per lattice row (96B rows, 32B aligned)
#define HBITS  21
#define HSIZE  (1u<<HBITS)     // 2M slots
#define HMASK  (HSIZE-1u)
#define KEMPTY 0xFFFFFFFFFFFFFFFFull

// ---- static device scratch (no runtime allocation allowed) ----
__device__ unsigned long long g_hkeys[HSIZE];
__device__ int                g_hvals[HSIZE];
__device__ unsigned long long g_rowkey[MAXLAT];
__device__ int                g_slot[NPT*DP1];
__device__ int                g_idx[NPT*DP1];
__device__ float              g_bary[NPT*DP1];
__device__ int                g_nbr[MAXLAT*12];   // 6 dirs x (plus,minus) per row
__device__ __align__(256) float g_lat0[MAXLAT*CPAD];
__device__ __align__(256) float g_lat1[MAXLAT*CPAD];
__device__ int                g_count;

__device__ __forceinline__ unsigned hhash(unsigned long long k){
    return (unsigned)((k * 0x9E3779B97F4A7C15ull) >> (64 - HBITS));
}

__device__ __forceinline__ int ht_insert(unsigned long long key){
    unsigned s = hhash(key);
    while (true){
        unsigned long long cur = g_hkeys[s];
        if (cur == key) return (int)s;
        if (cur == KEMPTY){
            unsigned long long old = atomicCAS(&g_hkeys[s], KEMPTY, key);
            if (old == KEMPTY || old == key) return (int)s;
        }
        s = (s + 1) & HMASK;
    }
}

__device__ __forceinline__ int ht_lookup(unsigned long long key){
    unsigned s = hhash(key);
    while (true){
        unsigned long long cur = g_hkeys[s];
        if (cur == key) return g_hvals[s];
        if (cur == KEMPTY) return -1;
        s = (s + 1) & HMASK;
    }
}

// ---- K0: reset hash table + counter (lattice zeroing deferred) ----
__global__ void k_init(){
    unsigned t = blockIdx.x * blockDim.x + threadIdx.x;
    unsigned stride = gridDim.x * blockDim.x;
    ulonglong2 e = make_ulonglong2(KEMPTY, KEMPTY);
    ulonglong2* hp = (ulonglong2*)g_hkeys;
    for (unsigned i = t; i < HSIZE/2; i += stride) hp[i] = e;
    if (t == 0) g_count = 0;
}

// ---- K1: per point: elevate, simplex, barycentric, key insert ----
__global__ void k_point(const float* __restrict__ img){
    int n = blockIdx.x * blockDim.x + threadIdx.x;
    if (n >= NPT) return;
    int b  = n >> 16;
    int hw = n & 65535;
    int h  = hw >> 8;
    int w  = hw & 255;

    const float* ip = img + b * 3 * HW + hw;
    float cf[5];
    cf[0] = ((float)w / 80.0f) * (float)3.4641016151377544;
    cf[1] = ((float)h / 80.0f) * (float)2.0;
    cf[2] = (ip[0]      / 13.0f) * (float)1.4142135623730951;
    cf[3] = (ip[HW]     / 13.0f) * (float)1.0954451150103321;
    cf[4] = (ip[2*HW]   / 13.0f) * (float)0.8944271909999159;

    float el[6];
    el[0] =  cf[0] + cf[1] + cf[2] + cf[3] + cf[4];
    el[1] = -1.f*cf[0] + cf[1] + cf[2] + cf[3] + cf[4];
    el[2] = -2.f*cf[1] + cf[2] + cf[3] + cf[4];
    el[3] = -3.f*cf[2] + cf[3] + cf[4];
    el[4] = -4.f*cf[3] + cf[4];
    el[5] = -5.f*cf[4];

    float rem0[6]; float s = 0.f;
#pragma unroll
    for (int j = 0; j < 6; j++){
        float v    = el[j] / 6.0f;
        float up   = ceilf(v)  * 6.0f;
        float down = floorf(v) * 6.0f;
        rem0[j] = ((up - el[j]) < (el[j] - down)) ? up : down;
        s += rem0[j];
    }
    int ssum = (int)rintf(s / 6.0f);

    float di[6];
#pragma unroll
    for (int j = 0; j < 6; j++) di[j] = el[j] - rem0[j];

    int rank[6];
#pragma unroll
    for (int i = 0; i < 6; i++){
        int r = 0;
#pragma unroll
        for (int j = 0; j < 6; j++){
            if (j == i) continue;
            if (j > i) r += (di[i] <  di[j]);
            else       r += (di[i] <= di[j]);
        }
        rank[i] = r + ssum;
    }
#pragma unroll
    for (int j = 0; j < 6; j++){
        if (rank[j] < 0)      { rank[j] += 6; rem0[j] += 6.f; }
        else if (rank[j] > 5) { rank[j] -= 6; rem0[j] -= 6.f; }
    }

    float bary[7] = {0.f,0.f,0.f,0.f,0.f,0.f,0.f};
#pragma unroll
    for (int i = 0; i < 6; i++){
        float t = (el[i] - rem0[i]) / 6.0f;
        bary[5 - rank[i]] += t;
        bary[6 - rank[i]] -= t;
    }
    bary[0] = (bary[0] + 1.0f) + bary[6];

    long long ri[5];
#pragma unroll
    for (int i = 0; i < 5; i++) ri[i] = (long long)llrintf(rem0[i]);

#pragma unroll
    for (int r = 0; r < 6; r++){
        g_bary[n*DP1 + r] = bary[r];
        long long pk = ((long long)b) << 60;
#pragma unroll
        for (int i = 0; i < 5; i++){
            long long ki = ri[i] + r - ((rank[i] > 5 - r) ? 6 : 0);
            pk += (ki + 2048) << (12 * i);
        }
        g_slot[n*DP1 + r] = ht_insert((unsigned long long)pk);
    }
}

// ---- K2: assign dense lattice indices (block-aggregated scan) ----
__global__ void k_assign(){
    const int SPT = 16;  // block covers 4096 slots
    __shared__ int wsum[8];
    __shared__ int blockBase;
    int t    = threadIdx.x;
    int base = blockIdx.x * (256 * SPT);

    int cnt = 0;
#pragma unroll
    for (int k = 0; k < SPT; k++)
        cnt += (g_hkeys[base + k*256 + t] != KEMPTY) ? 1 : 0;

    int lane = t & 31, wid = t >> 5;
    int pref = cnt;
#pragma unroll
    for (int off = 1; off < 32; off <<= 1){
        int y = __shfl_up_sync(0xffffffffu, pref, off);
        if (lane >= off) pref += y;
    }
    if (lane == 31) wsum[wid] = pref;
    __syncthreads();
    if (t < 8){
        int v = wsum[t];
#pragma unroll
        for (int off = 1; off < 8; off <<= 1){
            int y = __shfl_up_sync(0xffu, v, off);
            if (t >= off) v += y;
        }
        wsum[t] = v;
    }
    __syncthreads();
    if (t == 0) blockBase = atomicAdd(&g_count, wsum[7]);
    __syncthreads();

    int idx = blockBase + (wid ? wsum[wid-1] : 0) + (pref - cnt);
    for (int k = 0; k < SPT; k++){
        int sIdx = base + k*256 + t;
        unsigned long long key = g_hkeys[sIdx];
        if (key != KEMPTY){
            g_hvals[sIdx]  = idx;
            g_rowkey[idx]  = key;
            idx++;
        }
    }
}

// ---- K2b: zero only the live lattice rows ----
__global__ void k_zero(){
    int U = g_count;
    unsigned n4 = (unsigned)U * (CPAD/4);
    float4 z = make_float4(0.f,0.f,0.f,0.f);
    float4* p = (float4*)g_lat0;
    unsigned t = blockIdx.x * blockDim.x + threadIdx.x;
    unsigned stride = gridDim.x * blockDim.x;
    for (unsigned i = t; i < n4; i += stride) p[i] = z;
}

// ---- K2c: precompute all 12 neighbor indices per live row ----
__global__ void k_nbr(){
    int lane   = threadIdx.x & 31;
    int warp   = (blockIdx.x * blockDim.x + threadIdx.x) >> 5;
    int nwarps = (gridDim.x * blockDim.x) >> 5;
    int U = g_count;

    const long long ONES = 0x0001001001001001LL;  // +1 in each of 5 coord fields
    int j    = lane >> 1;    // direction 0..5 (lanes 0..11)
    int sgn  = lane & 1;     // 0 = +d1, 1 = -d1
    long long delta = (j < 5) ? (6LL << (12 * j)) : 0LL;
    long long d1 = ONES - delta;

    for (int i = warp; i < U; i += nwarps){
        unsigned long long key = g_rowkey[i];
        if (lane < 12){
            unsigned long long q = sgn ? (key - (unsigned long long)d1)
                                       : (key + (unsigned long long)d1);
            g_nbr[i*12 + lane] = ht_lookup(q);
        }
    }
}

// ---- K3: splat (warp per point; lanes = channels; coalesced atomics) ----
__global__ void k_splat(const float* __restrict__ x){
    int gw   = (blockIdx.x * blockDim.x + threadIdx.x) >> 5;
    int lane = threadIdx.x & 31;
    if (gw >= NPT) return;
    int n  = gw;
    int b  = n >> 16;
    int hw = n & 65535;

    float val = 0.f;
    if (lane < NC) val = x[(b*NC + lane) * HW + hw];

    int   myidx = 0;
    float myb   = 0.f;
    if (lane < DP1){
        int slot = g_slot[n*DP1 + lane];
        myidx = g_hvals[slot];
        g_idx[n*DP1 + lane] = myidx;
        myb   = g_bary[n*DP1 + lane];
    }
#pragma unroll
    for (int r = 0; r < DP1; r++){
        int   idx = __shfl_sync(0xffffffffu, myidx, r);
        float wgt = __shfl_sync(0xffffffffu, myb,   r);
        if (lane < NC) atomicAdd(&g_lat0[idx * CPAD + lane], wgt * val);
    }
}

// ---- K4: one blur pass along lattice direction j (precomputed neighbors) ----
__global__ void k_blur(int j){
    const float* __restrict__ in  = (j & 1) ? g_lat1 : g_lat0;
    float* __restrict__       out = (j & 1) ? g_lat0 : g_lat1;
    int lane   = threadIdx.x & 31;
    int warp   = (blockIdx.x * blockDim.x + threadIdx.x) >> 5;
    int nwarps = (gridDim.x * blockDim.x) >> 5;
    int U = g_count;

    const int2* __restrict__ nbr = (const int2*)g_nbr;

    for (int i = warp; i < U; i += nwarps){
        int2 nn = __ldg(&nbr[i*6 + j]);   // broadcast: all lanes same address
        if (lane < NC){
            float a  = in[i * CPAD + lane];
            float v1 = (nn.x >= 0) ? in[nn.x * CPAD + lane] : 0.f;
            float v2 = (nn.y >= 0) ? in[nn.y * CPAD + lane] : 0.f;
            out[i * CPAD + lane] = a + 0.5f * (v1 + v2);
        }
    }
}

// ---- K5: slice + transpose to NCHW output ----
__global__ void k_slice(float* __restrict__ out){
    __shared__ float sm[32][23];
    int warp = threadIdx.x >> 5, lane = threadIdx.x & 31;
    int n0 = blockIdx.x * 32;
    const float ALPHA = (float)(32.0 / 33.0);  // 1/(1+2^-5)

#pragma unroll
    for (int p = 0; p < 4; p++){
        int il = warp * 4 + p;
        int n  = n0 + il;
        int   myidx = 0;
        float myb   = 0.f;
        if (lane < DP1){
            myidx = g_idx[n*DP1 + lane];
            myb   = g_bary[n*DP1 + lane];
        }
        float acc = 0.f;
#pragma unroll
        for (int r = 0; r < DP1; r++){
            int   idx = __shfl_sync(0xffffffffu, myidx, r);
            float bw  = __shfl_sync(0xffffffffu, myb,   r);
            if (lane < NC) acc += bw * g_lat0[idx * CPAD + lane];
        }
        if (lane < NC) sm[il][lane] = ALPHA * acc;
    }
    __syncthreads();

    for (int t = threadIdx.x; t < NC * 32; t += 256){
        int c = t >> 5, i = t & 31;
        int n  = n0 + i;
        int b  = n >> 16;
        int hw = n & 65535;
        out[(b*NC + c) * HW + hw] = sm[i][c];
    }
}

extern "C" void kernel_launch(void* const* d_in, const int* in_sizes, int n_in,
                              void* d_out, int out_size){
    const float* x   = (const float*)d_in[0];   // (2,21,256,256)
    const float* img = (const float*)d_in[1];   // (2,3,256,256)
    float* out = (float*)d_out;

    k_init  <<<2048, 256>>>();
    k_point <<<NPT/256, 256>>>(img);
    k_assign<<<HSIZE/(256*16), 256>>>();
    k_zero  <<<4736, 256>>>();
    k_nbr   <<<4736, 256>>>();
    k_splat <<<NPT/8, 256>>>(x);
    for (int j = 0; j < 6; j++)
        k_blur<<<4736, 256>>>(j);
    k_slice <<<NPT/32, 256>>>(out);
}